// round 15
// baseline (speedup 1.0000x reference)
#include <cuda_runtime.h>
#include <cstdint>

#define NPART   100000
#define NFRAMES 500
#define BLOCK   256

__device__ __forceinline__ uint32_t rotl32(uint32_t x, int r) {
    return __funnelshift_l(x, x, r);  // single SHF
}

// Exact threefry2x32 (20 rounds, 5 key injections).
__device__ __forceinline__ void threefry_plain(uint32_t k0, uint32_t k1,
                                               uint32_t x0, uint32_t x1,
                                               uint32_t &o0, uint32_t &o1) {
    uint32_t ks2 = k0 ^ k1 ^ 0x1BD11BDAu;
    x0 += k0; x1 += k1;
#define RND(r) { x0 += x1; x1 = rotl32(x1, r); x1 ^= x0; }
    RND(13) RND(15) RND(26) RND(6)
    x0 += k1;  x1 += ks2 + 1u;
    RND(17) RND(29) RND(16) RND(24)
    x0 += ks2; x1 += k0 + 2u;
    RND(13) RND(15) RND(26) RND(6)
    x0 += k0;  x1 += k1 + 3u;
    RND(17) RND(29) RND(16) RND(24)
    x0 += k1;  x1 += ks2 + 4u;
    RND(13) RND(15) RND(26) RND(6)
    x0 += ks2; x1 += k0 + 5u;
#undef RND
    o0 = x0; o1 = x1;
}

// ceil-threshold: count of integers m with m * 2^-23 < X (exact pow2 scale).
__device__ __forceinline__ uint32_t thresh_from_prob(float p) {
    float X = p * 8388608.0f;
    uint32_t T = (uint32_t)X;
    if ((float)T < X) T++;
    return T;
}

// Single fused kernel: per-block key derivation (jax_threefry_partitionable,
// verified rel_err = 0) into shared memory, then the champion hot loop.
__global__ void __launch_bounds__(BLOCK)
hmm_kernel(const float* __restrict__ initial, const int* __restrict__ seed_ptr,
           float4* __restrict__ out) {
    __shared__ uint4    skeys[NFRAMES];     // (k0, k1, ks2, -)
    __shared__ uint32_t sthr[2];            // thresh << 9

    const int t = blockIdx.x * blockDim.x + threadIdx.x;

    // Hoisted input loads (clamped for pad threads): DRAM latency drains
    // behind the prologue threefry burst below.
    const int tc = (t < NPART / 2) ? t : (NPART / 2 - 1);
    const float iy = initial[4 * tc + 1];
    const float iw = initial[4 * tc + 3];

    // ---- prologue: every block derives all frame keys (cheap, parallel) ----
    {
        long long seed = (long long)(*seed_ptr);
        uint32_t k0 = (uint32_t)(((unsigned long long)seed) >> 32);
        uint32_t k1 = (uint32_t)seed;

        // split(key,2) foldlike: kp = tf(key,0,0), ks = tf(key,0,1)
        uint32_t kp0, kp1, ks0, ks1;
        threefry_plain(k0, k1, 0u, 0u, kp0, kp1);
        threefry_plain(k0, k1, 0u, 1u, ks0, ks1);

        // split(ks, 500) foldlike: keys[f] = tf(ks, 0, f)
        for (int i = threadIdx.x; i < NFRAMES; i += BLOCK) {
            uint32_t o0, o1;
            threefry_plain(ks0, ks1, 0u, (uint32_t)i, o0, o1);
            skeys[i] = make_uint4(o0, o1, o0 ^ o1 ^ 0x1BD11BDAu, 0u);
        }
        if (threadIdx.x == 0) {
            // p = uniform(kp, ()) * 0.001 ; bits = o0 ^ o1 under kp
            uint32_t o0, o1;
            threefry_plain(kp0, kp1, 0u, 0u, o0, o1);
            uint32_t bits = o0 ^ o1;
            float u = __uint_as_float((bits >> 9) | 0x3f800000u) - 1.0f;
            float p = u * 0.001f;
            sthr[0] = thresh_from_prob(0.2f) << 9;
            sthr[1] = thresh_from_prob(p) << 9;
        }
    }
    __syncthreads();

    if (t < NPART / 2) {
        const uint32_t t0s = sthr[0];
        const uint32_t t1s = sthr[1];

        uint32_t sa = (iy > 0.5f) ? 1u : 0u;
        uint32_t sb = (iw > 0.5f) ? 1u : 0u;

        const uint32_t ja_base = 4u * (uint32_t)t;
        const uint32_t jb_base = 4u * (uint32_t)t + 2u;

        float4* optr = out + t;

#pragma unroll 2
        for (int f = 0; f < NFRAMES; f++) {
            const uint4 key = skeys[f];               // LDS, uniform broadcast
            const uint32_t k0 = key.x, k1 = key.y, ks2 = key.z;

            uint32_t a0 = k0, a1 = (ja_base + sa) + k1;
            uint32_t b0 = k0, b1 = (jb_base + sb) + k1;

#define RND2(r) { a0 += a1; a1 = rotl32(a1, r) ^ a0; \
                  b0 += b1; b1 = rotl32(b1, r) ^ b0; }
#define INJ2(p0, p1, c) { a0 += (p0); a1 += (p1) + (c); \
                          b0 += (p0); b1 += (p1) + (c); }
            RND2(13) RND2(15) RND2(26) RND2(6)
            INJ2(k1, ks2, 1u)
            RND2(17) RND2(29) RND2(16) RND2(24)
            INJ2(ks2, k0, 2u)
            RND2(13) RND2(15) RND2(26) RND2(6)
            INJ2(k0, k1, 3u)
            RND2(17) RND2(29) RND2(16) RND2(24)
            INJ2(k1, ks2, 4u)
            RND2(13) RND2(15) RND2(26) RND2(6)
            INJ2(ks2, k0, 5u)
#undef RND2
#undef INJ2

            // folded compare: (x0^x1) < (th<<9)  ⟺  23-bit draw < th (exact)
            uint32_t va = a0 ^ a1;
            uint32_t vb = b0 ^ b1;
            sa ^= (va < (sa ? t1s : t0s)) ? 1u : 0u;
            sb ^= (vb < (sb ? t1s : t0s)) ? 1u : 0u;

            *optr = make_float4(sa ? 0.0f : 1.0f, sa ? 1.0f : 0.0f,
                                sb ? 0.0f : 1.0f, sb ? 1.0f : 0.0f);
            optr += NPART / 2;
        }
    }
}

extern "C" void kernel_launch(void* const* d_in, const int* in_sizes, int n_in,
                              void* d_out, int out_size) {
    const float* initial = (const float*)d_in[0];
    const int*   seed    = (const int*)d_in[1];
    float4*      out     = (float4*)d_out;
    (void)in_sizes; (void)n_in; (void)out_size;

    int threads_needed = NPART / 2;                     // 50000
    int blocks = (threads_needed + BLOCK - 1) / BLOCK;  // 196 blocks of 256
    hmm_kernel<<<blocks, BLOCK>>>(initial, seed, out);
}

// round 16
// speedup vs baseline: 1.2697x; 1.2697x over previous
#include <cuda_runtime.h>
#include <cstdint>

#define NPART   100000
#define NFRAMES 500
#define BLOCK   128

__device__ __forceinline__ uint32_t rotl32(uint32_t x, int r) {
    return __funnelshift_l(x, x, r);  // single SHF
}

// Exact threefry2x32 (20 rounds, 5 key injections).
__device__ __forceinline__ void threefry_plain(uint32_t k0, uint32_t k1,
                                               uint32_t x0, uint32_t x1,
                                               uint32_t &o0, uint32_t &o1) {
    uint32_t ks2 = k0 ^ k1 ^ 0x1BD11BDAu;
    x0 += k0; x1 += k1;
#define RND(r) { x0 += x1; x1 = rotl32(x1, r); x1 ^= x0; }
    RND(13) RND(15) RND(26) RND(6)
    x0 += k1;  x1 += ks2 + 1u;
    RND(17) RND(29) RND(16) RND(24)
    x0 += ks2; x1 += k0 + 2u;
    RND(13) RND(15) RND(26) RND(6)
    x0 += k0;  x1 += k1 + 3u;
    RND(17) RND(29) RND(16) RND(24)
    x0 += k1;  x1 += ks2 + 4u;
    RND(13) RND(15) RND(26) RND(6)
    x0 += ks2; x1 += k0 + 5u;
#undef RND
    o0 = x0; o1 = x1;
}

// ceil-threshold: count of integers m with m * 2^-23 < X (exact pow2 scale).
__device__ __forceinline__ uint32_t thresh_from_prob(float p) {
    float X = p * 8388608.0f;
    uint32_t T = (uint32_t)X;
    if ((float)T < X) T++;
    return T;
}

// Single fused kernel: per-block key derivation (jax_threefry_partitionable,
// verified rel_err = 0) into shared memory, then the champion hot loop.
// Block 128 / 391 blocks: binding SMs carry 3 blocks (imbalance 1.14, proven
// optimal partition of 5.28 warp-chain-units/SMSP into integer warps).
__global__ void __launch_bounds__(BLOCK)
hmm_kernel(const float* __restrict__ initial, const int* __restrict__ seed_ptr,
           float4* __restrict__ out) {
    __shared__ uint4    skeys[NFRAMES];     // (k0, k1, ks2, -)
    __shared__ uint32_t sthr[2];            // thresh << 9

    const int t = blockIdx.x * blockDim.x + threadIdx.x;

    // Hoisted input loads (clamped for pad threads): DRAM latency drains
    // behind the prologue threefry burst below. (Measured neutral-safe, R15.)
    const int tc = (t < NPART / 2) ? t : (NPART / 2 - 1);
    const float iy = initial[4 * tc + 1];
    const float iw = initial[4 * tc + 3];

    // ---- prologue: every block derives all frame keys (cheap, parallel) ----
    {
        long long seed = (long long)(*seed_ptr);
        uint32_t k0 = (uint32_t)(((unsigned long long)seed) >> 32);
        uint32_t k1 = (uint32_t)seed;

        // split(key,2) foldlike: kp = tf(key,0,0), ks = tf(key,0,1)
        uint32_t kp0, kp1, ks0, ks1;
        threefry_plain(k0, k1, 0u, 0u, kp0, kp1);
        threefry_plain(k0, k1, 0u, 1u, ks0, ks1);

        // split(ks, 500) foldlike: keys[f] = tf(ks, 0, f)
        for (int i = threadIdx.x; i < NFRAMES; i += BLOCK) {
            uint32_t o0, o1;
            threefry_plain(ks0, ks1, 0u, (uint32_t)i, o0, o1);
            skeys[i] = make_uint4(o0, o1, o0 ^ o1 ^ 0x1BD11BDAu, 0u);
        }
        if (threadIdx.x == 0) {
            // p = uniform(kp, ()) * 0.001 ; bits = o0 ^ o1 under kp
            uint32_t o0, o1;
            threefry_plain(kp0, kp1, 0u, 0u, o0, o1);
            uint32_t bits = o0 ^ o1;
            float u = __uint_as_float((bits >> 9) | 0x3f800000u) - 1.0f;
            float p = u * 0.001f;
            sthr[0] = thresh_from_prob(0.2f) << 9;
            sthr[1] = thresh_from_prob(p) << 9;
        }
    }
    __syncthreads();

    if (t < NPART / 2) {
        const uint32_t t0s = sthr[0];
        const uint32_t t1s = sthr[1];

        uint32_t sa = (iy > 0.5f) ? 1u : 0u;
        uint32_t sb = (iw > 0.5f) ? 1u : 0u;

        const uint32_t ja_base = 4u * (uint32_t)t;
        const uint32_t jb_base = 4u * (uint32_t)t + 2u;

        float4* optr = out + t;

#pragma unroll 2
        for (int f = 0; f < NFRAMES; f++) {
            const uint4 key = skeys[f];               // LDS, uniform broadcast
            const uint32_t k0 = key.x, k1 = key.y, ks2 = key.z;

            uint32_t a0 = k0, a1 = (ja_base + sa) + k1;
            uint32_t b0 = k0, b1 = (jb_base + sb) + k1;

#define RND2(r) { a0 += a1; a1 = rotl32(a1, r) ^ a0; \
                  b0 += b1; b1 = rotl32(b1, r) ^ b0; }
#define INJ2(p0, p1, c) { a0 += (p0); a1 += (p1) + (c); \
                          b0 += (p0); b1 += (p1) + (c); }
            RND2(13) RND2(15) RND2(26) RND2(6)
            INJ2(k1, ks2, 1u)
            RND2(17) RND2(29) RND2(16) RND2(24)
            INJ2(ks2, k0, 2u)
            RND2(13) RND2(15) RND2(26) RND2(6)
            INJ2(k0, k1, 3u)
            RND2(17) RND2(29) RND2(16) RND2(24)
            INJ2(k1, ks2, 4u)
            RND2(13) RND2(15) RND2(26) RND2(6)
            INJ2(ks2, k0, 5u)
#undef RND2
#undef INJ2

            // folded compare: (x0^x1) < (th<<9)  ⟺  23-bit draw < th (exact)
            uint32_t va = a0 ^ a1;
            uint32_t vb = b0 ^ b1;
            sa ^= (va < (sa ? t1s : t0s)) ? 1u : 0u;
            sb ^= (vb < (sb ? t1s : t0s)) ? 1u : 0u;

            *optr = make_float4(sa ? 0.0f : 1.0f, sa ? 1.0f : 0.0f,
                                sb ? 0.0f : 1.0f, sb ? 1.0f : 0.0f);
            optr += NPART / 2;
        }
    }
}

extern "C" void kernel_launch(void* const* d_in, const int* in_sizes, int n_in,
                              void* d_out, int out_size) {
    const float* initial = (const float*)d_in[0];
    const int*   seed    = (const int*)d_in[1];
    float4*      out     = (float4*)d_out;
    (void)in_sizes; (void)n_in; (void)out_size;

    int threads_needed = NPART / 2;                     // 50000
    int blocks = (threads_needed + BLOCK - 1) / BLOCK;  // 391 blocks of 128
    hmm_kernel<<<blocks, BLOCK>>>(initial, seed, out);
}

// round 17
// speedup vs baseline: 1.3102x; 1.0319x over previous
#include <cuda_runtime.h>
#include <cstdint>

#define NPART   100000
#define NFRAMES 500
#define BLOCK   128

__device__ __forceinline__ uint32_t rotl32(uint32_t x, int r) {
    return __funnelshift_l(x, x, r);  // single SHF
}

// Exact threefry2x32 (20 rounds, 5 key injections).
__device__ __forceinline__ void threefry_plain(uint32_t k0, uint32_t k1,
                                               uint32_t x0, uint32_t x1,
                                               uint32_t &o0, uint32_t &o1) {
    uint32_t ks2 = k0 ^ k1 ^ 0x1BD11BDAu;
    x0 += k0; x1 += k1;
#define RND(r) { x0 += x1; x1 = rotl32(x1, r); x1 ^= x0; }
    RND(13) RND(15) RND(26) RND(6)
    x0 += k1;  x1 += ks2 + 1u;
    RND(17) RND(29) RND(16) RND(24)
    x0 += ks2; x1 += k0 + 2u;
    RND(13) RND(15) RND(26) RND(6)
    x0 += k0;  x1 += k1 + 3u;
    RND(17) RND(29) RND(16) RND(24)
    x0 += k1;  x1 += ks2 + 4u;
    RND(13) RND(15) RND(26) RND(6)
    x0 += ks2; x1 += k0 + 5u;
#undef RND
    o0 = x0; o1 = x1;
}

// ceil-threshold: count of integers m with m * 2^-23 < X (exact pow2 scale).
__device__ __forceinline__ uint32_t thresh_from_prob(float p) {
    float X = p * 8388608.0f;
    uint32_t T = (uint32_t)X;
    if ((float)T < X) T++;
    return T;
}

// Single fused kernel: per-block key derivation (jax_threefry_partitionable,
// verified rel_err = 0) into shared memory, then the champion hot loop.
// Block 128 / 391 blocks: binding SMSPs carry 3 warps (imbalance 1.14 —
// proven lower bound for 100000 particles at 32-lane warp granularity).
__global__ void __launch_bounds__(BLOCK)
hmm_kernel(const float* __restrict__ initial, const int* __restrict__ seed_ptr,
           float4* __restrict__ out) {
    __shared__ uint4    skeys[NFRAMES];     // (k0, k1, ks2, -)
    __shared__ uint32_t sthr[2];            // thresh << 9

    const int t = blockIdx.x * blockDim.x + threadIdx.x;

    // Hoisted input loads (clamped for pad threads): DRAM latency drains
    // behind the prologue threefry burst below.
    const int tc = (t < NPART / 2) ? t : (NPART / 2 - 1);
    const float iy = initial[4 * tc + 1];
    const float iw = initial[4 * tc + 3];

    // ---- prologue: every block derives all frame keys (cheap, parallel) ----
    {
        long long seed = (long long)(*seed_ptr);
        uint32_t k0 = (uint32_t)(((unsigned long long)seed) >> 32);
        uint32_t k1 = (uint32_t)seed;

        // split(key,2) foldlike: kp = tf(key,0,0), ks = tf(key,0,1)
        uint32_t kp0, kp1, ks0, ks1;
        threefry_plain(k0, k1, 0u, 0u, kp0, kp1);
        threefry_plain(k0, k1, 0u, 1u, ks0, ks1);

        // split(ks, 500) foldlike: keys[f] = tf(ks, 0, f)
        for (int i = threadIdx.x; i < NFRAMES; i += BLOCK) {
            uint32_t o0, o1;
            threefry_plain(ks0, ks1, 0u, (uint32_t)i, o0, o1);
            skeys[i] = make_uint4(o0, o1, o0 ^ o1 ^ 0x1BD11BDAu, 0u);
        }
        if (threadIdx.x == 0) {
            // p = uniform(kp, ()) * 0.001 ; bits = o0 ^ o1 under kp
            uint32_t o0, o1;
            threefry_plain(kp0, kp1, 0u, 0u, o0, o1);
            uint32_t bits = o0 ^ o1;
            float u = __uint_as_float((bits >> 9) | 0x3f800000u) - 1.0f;
            float p = u * 0.001f;
            sthr[0] = thresh_from_prob(0.2f) << 9;
            sthr[1] = thresh_from_prob(p) << 9;
        }
    }
    __syncthreads();

    if (t < NPART / 2) {
        const uint32_t t0s = sthr[0];
        const uint32_t t1s = sthr[1];

        uint32_t sa = (iy > 0.5f) ? 1u : 0u;
        uint32_t sb = (iw > 0.5f) ? 1u : 0u;

        const uint32_t ja_base = 4u * (uint32_t)t;
        const uint32_t jb_base = 4u * (uint32_t)t + 2u;

        float4* optr = out + t;

#pragma unroll 5
        for (int f = 0; f < NFRAMES; f++) {
            const uint4 key = skeys[f];               // LDS, uniform broadcast
            const uint32_t k0 = key.x, k1 = key.y, ks2 = key.z;

            uint32_t a0 = k0, a1 = (ja_base + sa) + k1;
            uint32_t b0 = k0, b1 = (jb_base + sb) + k1;

#define RND2(r) { a0 += a1; a1 = rotl32(a1, r) ^ a0; \
                  b0 += b1; b1 = rotl32(b1, r) ^ b0; }
#define INJ2(p0, p1, c) { a0 += (p0); a1 += (p1) + (c); \
                          b0 += (p0); b1 += (p1) + (c); }
            RND2(13) RND2(15) RND2(26) RND2(6)
            INJ2(k1, ks2, 1u)
            RND2(17) RND2(29) RND2(16) RND2(24)
            INJ2(ks2, k0, 2u)
            RND2(13) RND2(15) RND2(26) RND2(6)
            INJ2(k0, k1, 3u)
            RND2(17) RND2(29) RND2(16) RND2(24)
            INJ2(k1, ks2, 4u)
            RND2(13) RND2(15) RND2(26) RND2(6)
            INJ2(ks2, k0, 5u)
#undef RND2
#undef INJ2

            // folded compare: (x0^x1) < (th<<9)  ⟺  23-bit draw < th (exact)
            uint32_t va = a0 ^ a1;
            uint32_t vb = b0 ^ b1;
            sa ^= (va < (sa ? t1s : t0s)) ? 1u : 0u;
            sb ^= (vb < (sb ? t1s : t0s)) ? 1u : 0u;

            *optr = make_float4(sa ? 0.0f : 1.0f, sa ? 1.0f : 0.0f,
                                sb ? 0.0f : 1.0f, sb ? 1.0f : 0.0f);
            optr += NPART / 2;
        }
    }
}

extern "C" void kernel_launch(void* const* d_in, const int* in_sizes, int n_in,
                              void* d_out, int out_size) {
    const float* initial = (const float*)d_in[0];
    const int*   seed    = (const int*)d_in[1];
    float4*      out     = (float4*)d_out;
    (void)in_sizes; (void)n_in; (void)out_size;

    int threads_needed = NPART / 2;                     // 50000
    int blocks = (threads_needed + BLOCK - 1) / BLOCK;  // 391 blocks of 128
    hmm_kernel<<<blocks, BLOCK>>>(initial, seed, out);
}